// round 4
// baseline (speedup 1.0000x reference)
#include <cuda_runtime.h>
#include <cuda_bf16.h>
#include <cstdint>
#include <math.h>

#define Bn 4
#define Cn 64
#define Hn 96
#define Wn 96
#define HWn (Hn*Wn)
#define KKn 9

typedef unsigned long long ull;

// Scratch (device globals -- no dynamic allocation allowed)
__device__ __align__(16) float g_xt[Bn*HWn*Cn];   // x in NHWC: [b][h][w][c]
__device__ __align__(16) float g_offs[Bn*HWn*27]; // per pixel: 9 x (dy,dx,sig(mask))
__device__ __align__(16) float g_wt[KKn*Cn*Cn];   // [kk][c][o]
__device__ __align__(16) float g_wt2[Cn*KKn*28];  // om weights: [c][t][28-padded oc]

// ---------------- packed f32x2 helpers (register-only) ----------------
__device__ __forceinline__ ull pk2(float a, float b) {
    ull r; asm("mov.b64 %0, {%1, %2};" : "=l"(r) : "f"(a), "f"(b)); return r;
}
__device__ __forceinline__ void fma2(ull& d, ull a, ull b) {
    asm("fma.rn.f32x2 %0, %1, %2, %0;" : "+l"(d) : "l"(a), "l"(b));
}
__device__ __forceinline__ ull mul2(ull a, ull b) {
    ull r; asm("mul.rn.f32x2 %0, %1, %2;" : "=l"(r) : "l"(a), "l"(b)); return r;
}
__device__ __forceinline__ void upk2(ull v, float& a, float& b) {
    asm("mov.b64 {%0, %1}, %2;" : "=f"(a), "=f"(b) : "l"(v));
}

// ---------------------------------------------------------------------------
// K0: NCHW -> NHWC transpose of x
// ---------------------------------------------------------------------------
__global__ void transpose_k(const float* __restrict__ x) {
    __shared__ __align__(16) float tile[32][33];
    int hw0 = blockIdx.x * 32;
    int c0  = blockIdx.y * 32;
    int b   = blockIdx.z;
    int tx = threadIdx.x, ty = threadIdx.y;
    const float* xb = x + (size_t)b * Cn * HWn;
#pragma unroll
    for (int i = 0; i < 4; i++) {
        int cc = c0 + ty + i * 8;
        tile[ty + i * 8][tx] = xb[(size_t)cc * HWn + hw0 + tx];
    }
    __syncthreads();
    float* xtb = g_xt + (size_t)b * HWn * Cn;
#pragma unroll
    for (int i = 0; i < 4; i++) {
        int hw = hw0 + ty + i * 8;
        xtb[(size_t)hw * Cn + c0 + tx] = tile[tx][ty + i * 8];
    }
}

// ---------------------------------------------------------------------------
// K0b: weight prep.  g_wt[kk][c][o],  g_wt2[c][t][28]
// ---------------------------------------------------------------------------
__global__ void prep_w_k(const float* __restrict__ w_conv,
                         const float* __restrict__ w_om) {
    int i = blockIdx.x * blockDim.x + threadIdx.x;
    if (i < KKn * Cn * Cn) {
        int kk = i / (Cn * Cn);
        int rem = i - kk * Cn * Cn;
        int c = rem / Cn;
        int o = rem - c * Cn;
        g_wt[i] = w_conv[(o * Cn + c) * KKn + kk];
    }
    if (i < Cn * KKn * 28) {
        int c = i / (KKn * 28);
        int r = i - c * (KKn * 28);
        int t = r / 28;
        int oc = r - t * 28;
        g_wt2[i] = (oc < 27) ? w_om[(oc * Cn + c) * KKn + t] : 0.f;
    }
}

// ---------------------------------------------------------------------------
// K1: offset/mask conv (27 out ch, 3x3, pad 1) + bias + sigmoid(mask)
// 16x16 pixel tile, 256 threads; 4 channels per staging step; f32x2 FMA
// ---------------------------------------------------------------------------
__global__ void __launch_bounds__(256) om_conv_k(const float* __restrict__ x,
                                                 const float* __restrict__ b_om) {
    __shared__ __align__(16) float xs[4][324];   // 4 channels of 18x18 tile
    __shared__ __align__(16) float ws[4 * 252];  // 4 channels of [t][28]

    int b  = blockIdx.z;
    int h0 = blockIdx.y * 16;
    int w0 = blockIdx.x * 16;
    int tid = threadIdx.x;
    int tx = tid & 15, ty = tid >> 4;

    ull acc2[14];
#pragma unroll
    for (int i = 0; i < 14; i++) acc2[i] = 0ull;

    const float* xb = x + (size_t)b * Cn * HWn;

    for (int c0 = 0; c0 < Cn; c0 += 4) {
        __syncthreads();
        // stage 4 channels of 18x18 x tile
        for (int i = tid; i < 1296; i += 256) {
            int ch = i / 324;
            int rem = i - ch * 324;
            int r = rem / 18, cc = rem - r * 18;
            int gh = h0 - 1 + r, gw = w0 - 1 + cc;
            float v = 0.f;
            if (gh >= 0 && gh < Hn && gw >= 0 && gw < Wn)
                v = xb[(size_t)(c0 + ch) * HWn + gh * Wn + gw];
            xs[ch][rem] = v;
        }
        // stage 4 channels of weights: fully coalesced float4
        {
            const float4* src = (const float4*)(g_wt2 + c0 * (KKn * 28));
            float4* dst = (float4*)ws;
            if (tid < 252) dst[tid] = src[tid];
        }
        __syncthreads();

#pragma unroll
        for (int ch = 0; ch < 4; ch++) {
            float xv[9];
#pragma unroll
            for (int t = 0; t < 9; t++)
                xv[t] = xs[ch][(ty + t / 3) * 18 + tx + (t % 3)];
#pragma unroll
            for (int t = 0; t < 9; t++) {
                ull xd = pk2(xv[t], xv[t]);
#pragma unroll
                for (int q = 0; q < 7; q++) {
                    float4 w4 = *(const float4*)&ws[ch * 252 + t * 28 + q * 4];
                    ull wlo = pk2(w4.x, w4.y);
                    ull whi = pk2(w4.z, w4.w);
                    fma2(acc2[2 * q], xd, wlo);
                    fma2(acc2[2 * q + 1], xd, whi);
                }
            }
        }
    }

    float acc[28];
#pragma unroll
    for (int j = 0; j < 14; j++) upk2(acc2[j], acc[2 * j], acc[2 * j + 1]);

    int h = h0 + ty, w = w0 + tx;
    float* op = g_offs + ((size_t)b * HWn + h * Wn + w) * 27;
#pragma unroll
    for (int kk = 0; kk < 9; kk++) {
        float dy = acc[2 * kk]     + b_om[2 * kk];
        float dx = acc[2 * kk + 1] + b_om[2 * kk + 1];
        float mv = acc[18 + kk]    + b_om[18 + kk];
        mv = 1.f / (1.f + expf(-mv));
        op[3 * kk]     = dy;
        op[3 * kk + 1] = dx;
        op[3 * kk + 2] = mv;
    }
}

// ---------------------------------------------------------------------------
// K2: fused bilinear sampling + (pix x o) GEMM + BN + SiLU
// block: 64 pixel tile x 64 o, 256 threads, 4pix x 4o micro-tile, f32x2
// Full 64-channel staging per kk -> 2 barriers per kk
// ---------------------------------------------------------------------------
__global__ void __launch_bounds__(256) main_k(const float* __restrict__ gamma,
                                              const float* __restrict__ beta,
                                              const float* __restrict__ rmean,
                                              const float* __restrict__ rvar,
                                              float* __restrict__ out) {
    __shared__ __align__(16) int   s_off[4][64];  // 4 corner offsets per pixel
    __shared__ __align__(16) float s_bw[4][64];   // 4 folded bilinear weights
    __shared__ __align__(16) float sA[64 * 68];   // sampled [c][pix], stride 68
    __shared__ __align__(16) float sW[64 * 64];   // w tile [c][o]

    int b  = blockIdx.z;
    int h0 = blockIdx.y * 4;
    int w0 = blockIdx.x * 16;
    int tid = threadIdx.x;
    int o_grp = tid & 15;      // o micro-tile -> o0 = o_grp*4
    int p_grp = tid >> 4;      // pix micro-tile -> pix0 = p_grp*4
    int pix = tid >> 2, cv = tid & 3;   // staging roles

    ull acc2[8];
#pragma unroll
    for (int i = 0; i < 8; i++) acc2[i] = 0ull;

    const float* xb = g_xt + (size_t)b * HWn * Cn;

    for (int kk = 0; kk < 9; kk++) {
        // --- per-kk coords: 64 threads, one per pixel ---
        if (tid < 64) {
            int prow = tid >> 4, pcol = tid & 15;
            int ho = h0 + prow, wo = w0 + pcol;
            const float* op = g_offs + ((size_t)b * HWn + ho * Wn + wo) * 27 + 3 * kk;
            float dy = op[0], dx = op[1], m = op[2];
            float py = (float)(ho - 1 + kk / 3) + dy;
            float px = (float)(wo - 1 + kk % 3) + dx;
            float y0f = floorf(py), x0f = floorf(px);
            float ly = py - y0f, lx = px - x0f;
            int y0 = (int)y0f, x0 = (int)x0f;
            int y1 = y0 + 1, x1 = x0 + 1;
            float vy0 = (y0 >= 0 && y0 < Hn) ? 1.f : 0.f;
            float vy1 = (y1 >= 0 && y1 < Hn) ? 1.f : 0.f;
            float vx0 = (x0 >= 0 && x0 < Wn) ? 1.f : 0.f;
            float vx1 = (x1 >= 0 && x1 < Wn) ? 1.f : 0.f;
            s_bw[0][tid] = (1.f - ly) * (1.f - lx) * m * vy0 * vx0;
            s_bw[1][tid] = (1.f - ly) * lx         * m * vy0 * vx1;
            s_bw[2][tid] = ly * (1.f - lx)         * m * vy1 * vx0;
            s_bw[3][tid] = ly * lx                 * m * vy1 * vx1;
            int y0c = min(max(y0, 0), Hn - 1), y1c = min(max(y1, 0), Hn - 1);
            int x0c = min(max(x0, 0), Wn - 1), x1c = min(max(x1, 0), Wn - 1);
            s_off[0][tid] = (y0c * Wn + x0c) * Cn;
            s_off[1][tid] = (y0c * Wn + x1c) * Cn;
            s_off[2][tid] = (y1c * Wn + x0c) * Cn;
            s_off[3][tid] = (y1c * Wn + x1c) * Cn;
        }
        __syncthreads();

        // --- stage full 64-channel sampled tile sA + W tile sW ---
        {
            int q00 = s_off[0][pix], q01 = s_off[1][pix];
            int q10 = s_off[2][pix], q11 = s_off[3][pix];
            float b00 = s_bw[0][pix], b01 = s_bw[1][pix];
            float b10 = s_bw[2][pix], b11 = s_bw[3][pix];
            ull pw00 = pk2(b00, b00), pw01 = pk2(b01, b01);
            ull pw10 = pk2(b10, b10), pw11 = pk2(b11, b11);
#pragma unroll
            for (int cg = 0; cg < 4; cg++) {
                int c = cg * 16 + cv * 4;
                float4 v00 = *(const float4*)(xb + q00 + c);
                float4 v01 = *(const float4*)(xb + q01 + c);
                float4 v10 = *(const float4*)(xb + q10 + c);
                float4 v11 = *(const float4*)(xb + q11 + c);
                ull r0 = mul2(pw00, pk2(v00.x, v00.y));
                fma2(r0, pw01, pk2(v01.x, v01.y));
                fma2(r0, pw10, pk2(v10.x, v10.y));
                fma2(r0, pw11, pk2(v11.x, v11.y));
                ull r1 = mul2(pw00, pk2(v00.z, v00.w));
                fma2(r1, pw01, pk2(v01.z, v01.w));
                fma2(r1, pw10, pk2(v10.z, v10.w));
                fma2(r1, pw11, pk2(v11.z, v11.w));
                float f0, f1, f2, f3;
                upk2(r0, f0, f1); upk2(r1, f2, f3);
                sA[(c + 0) * 68 + pix] = f0;
                sA[(c + 1) * 68 + pix] = f1;
                sA[(c + 2) * 68 + pix] = f2;
                sA[(c + 3) * 68 + pix] = f3;
            }
            // W tile: 4096 floats, coalesced float4
            const float4* src = (const float4*)(g_wt + kk * Cn * Cn);
            float4* dst = (float4*)sW;
#pragma unroll
            for (int i = 0; i < 4; i++) dst[tid + i * 256] = src[tid + i * 256];
        }
        __syncthreads();

        // --- GEMM: 64 K-steps, packed f32x2 ---
#pragma unroll 16
        for (int cl = 0; cl < 64; cl++) {
            float4 sv = *(const float4*)&sA[cl * 68 + p_grp * 4];
            float4 wv = *(const float4*)&sW[cl * 64 + o_grp * 4];
            ull wlo = pk2(wv.x, wv.y), whi = pk2(wv.z, wv.w);
            ull sp0 = pk2(sv.x, sv.x), sp1 = pk2(sv.y, sv.y);
            ull sp2 = pk2(sv.z, sv.z), sp3 = pk2(sv.w, sv.w);
            fma2(acc2[0], sp0, wlo); fma2(acc2[1], sp0, whi);
            fma2(acc2[2], sp1, wlo); fma2(acc2[3], sp1, whi);
            fma2(acc2[4], sp2, wlo); fma2(acc2[5], sp2, whi);
            fma2(acc2[6], sp3, wlo); fma2(acc2[7], sp3, whi);
        }
    }

    // --- epilogue: BN + SiLU, write NCHW ---
    float acc[16];
#pragma unroll
    for (int p = 0; p < 4; p++) {
        upk2(acc2[p * 2 + 0], acc[p * 4 + 0], acc[p * 4 + 1]);
        upk2(acc2[p * 2 + 1], acc[p * 4 + 2], acc[p * 4 + 3]);
    }

    int o0 = o_grp * 4;
    int prow = p_grp >> 2;
    int col0 = (p_grp & 3) * 4;
    int ho = h0 + prow, wo = w0 + col0;
#pragma unroll
    for (int j = 0; j < 4; j++) {
        int o = o0 + j;
        float sc = gamma[o] * rsqrtf(rvar[o] + 1e-5f);
        float sh = beta[o] - rmean[o] * sc;
        float4 r;
        float v;
        v = acc[0 * 4 + j] * sc + sh; r.x = v / (1.f + expf(-v));
        v = acc[1 * 4 + j] * sc + sh; r.y = v / (1.f + expf(-v));
        v = acc[2 * 4 + j] * sc + sh; r.z = v / (1.f + expf(-v));
        v = acc[3 * 4 + j] * sc + sh; r.w = v / (1.f + expf(-v));
        *(float4*)&out[(((size_t)b * Cn + o) * Hn + ho) * Wn + wo] = r;
    }
}

// ---------------------------------------------------------------------------
extern "C" void kernel_launch(void* const* d_in, const int* in_sizes, int n_in,
                              void* d_out, int out_size) {
    const float* x      = (const float*)d_in[0];
    const float* w_om   = (const float*)d_in[1];
    const float* b_om   = (const float*)d_in[2];
    const float* w_conv = (const float*)d_in[3];
    const float* gamma  = (const float*)d_in[4];
    const float* beta   = (const float*)d_in[5];
    const float* rmean  = (const float*)d_in[6];
    const float* rvar   = (const float*)d_in[7];
    float* out = (float*)d_out;

    transpose_k<<<dim3(HWn / 32, Cn / 32, Bn), dim3(32, 8)>>>(x);
    prep_w_k<<<(KKn * Cn * Cn + 1023) / 1024, 1024>>>(w_conv, w_om);
    om_conv_k<<<dim3(Wn / 16, Hn / 16, Bn), 256>>>(x, b_om);
    main_k<<<dim3(Wn / 16, Hn / 4, Bn), 256>>>(gamma, beta, rmean, rvar, out);
}

// round 6
// speedup vs baseline: 1.0978x; 1.0978x over previous
#include <cuda_runtime.h>
#include <cuda_bf16.h>
#include <cstdint>
#include <math.h>

#define Bn 4
#define Cn 64
#define Hn 96
#define Wn 96
#define HWn (Hn*Wn)
#define KKn 9

typedef unsigned long long ull;

// Scratch (device globals -- no dynamic allocation allowed)
__device__ __align__(16) float g_xt[Bn*HWn*Cn];   // x in NHWC: [b][h][w][c]
__device__ __align__(16) float g_offs[Bn*HWn*27]; // per pixel: 9 x (dy,dx,sig(mask))
__device__ __align__(16) float g_wt[KKn*Cn*Cn];   // [kk][c][o]
__device__ __align__(16) float g_wt2[Cn*KKn*28];  // om weights: [c][t][28-padded oc]

// main_k dynamic smem layout (bytes):
//   [0,      2048)   s_off : int  [4][128]
//   [2048,   4096)   s_bw  : float[4][128]
//   [4096,  37888)   sA    : float[64][132]
//   [37888, 54272)   sW    : float[64][64]
#define MAINK_SMEM 54272

// ---------------- packed f32x2 helpers (register-only) ----------------
__device__ __forceinline__ ull pk2(float a, float b) {
    ull r; asm("mov.b64 %0, {%1, %2};" : "=l"(r) : "f"(a), "f"(b)); return r;
}
__device__ __forceinline__ void fma2(ull& d, ull a, ull b) {
    asm("fma.rn.f32x2 %0, %1, %2, %0;" : "+l"(d) : "l"(a), "l"(b));
}
__device__ __forceinline__ ull mul2(ull a, ull b) {
    ull r; asm("mul.rn.f32x2 %0, %1, %2;" : "=l"(r) : "l"(a), "l"(b)); return r;
}
__device__ __forceinline__ void upk2(ull v, float& a, float& b) {
    asm("mov.b64 {%0, %1}, %2;" : "=f"(a), "=f"(b) : "l"(v));
}

// ---------------------------------------------------------------------------
// K0: NCHW -> NHWC transpose of x
// ---------------------------------------------------------------------------
__global__ void transpose_k(const float* __restrict__ x) {
    __shared__ __align__(16) float tile[32][33];
    int hw0 = blockIdx.x * 32;
    int c0  = blockIdx.y * 32;
    int b   = blockIdx.z;
    int tx = threadIdx.x, ty = threadIdx.y;
    const float* xb = x + (size_t)b * Cn * HWn;
#pragma unroll
    for (int i = 0; i < 4; i++) {
        int cc = c0 + ty + i * 8;
        tile[ty + i * 8][tx] = xb[(size_t)cc * HWn + hw0 + tx];
    }
    __syncthreads();
    float* xtb = g_xt + (size_t)b * HWn * Cn;
#pragma unroll
    for (int i = 0; i < 4; i++) {
        int hw = hw0 + ty + i * 8;
        xtb[(size_t)hw * Cn + c0 + tx] = tile[tx][ty + i * 8];
    }
}

// ---------------------------------------------------------------------------
// K0b: weight prep.  g_wt[kk][c][o],  g_wt2[c][t][28]
// ---------------------------------------------------------------------------
__global__ void prep_w_k(const float* __restrict__ w_conv,
                         const float* __restrict__ w_om) {
    int i = blockIdx.x * blockDim.x + threadIdx.x;
    if (i < KKn * Cn * Cn) {
        int kk = i / (Cn * Cn);
        int rem = i - kk * Cn * Cn;
        int c = rem / Cn;
        int o = rem - c * Cn;
        g_wt[i] = w_conv[(o * Cn + c) * KKn + kk];
    }
    if (i < Cn * KKn * 28) {
        int c = i / (KKn * 28);
        int r = i - c * (KKn * 28);
        int t = r / 28;
        int oc = r - t * 28;
        g_wt2[i] = (oc < 27) ? w_om[(oc * Cn + c) * KKn + t] : 0.f;
    }
}

// ---------------------------------------------------------------------------
// K1: offset/mask conv (27 out ch, 3x3, pad 1) + bias + sigmoid(mask)
// 16x16 pixel tile, 256 threads; 8 channels per staging step; f32x2 FMA
// ---------------------------------------------------------------------------
__global__ void __launch_bounds__(256) om_conv_k(const float* __restrict__ x,
                                                 const float* __restrict__ b_om) {
    __shared__ __align__(16) float xs[8][324];   // 8 channels of 18x18 tile
    __shared__ __align__(16) float ws[8 * 252];  // 8 channels of [t][28]

    int b  = blockIdx.z;
    int h0 = blockIdx.y * 16;
    int w0 = blockIdx.x * 16;
    int tid = threadIdx.x;
    int tx = tid & 15, ty = tid >> 4;

    ull acc2[14];
#pragma unroll
    for (int i = 0; i < 14; i++) acc2[i] = 0ull;

    const float* xb = x + (size_t)b * Cn * HWn;

    for (int c0 = 0; c0 < Cn; c0 += 8) {
        __syncthreads();
        // stage 8 channels of 18x18 x tile
        for (int i = tid; i < 2592; i += 256) {
            int ch = i / 324;
            int rem = i - ch * 324;
            int r = rem / 18, cc = rem - r * 18;
            int gh = h0 - 1 + r, gw = w0 - 1 + cc;
            float v = 0.f;
            if (gh >= 0 && gh < Hn && gw >= 0 && gw < Wn)
                v = xb[(size_t)(c0 + ch) * HWn + gh * Wn + gw];
            xs[ch][rem] = v;
        }
        // stage 8 channels of weights: fully coalesced float4 (504 vec4)
        {
            const float4* src = (const float4*)(g_wt2 + c0 * (KKn * 28));
            float4* dst = (float4*)ws;
            dst[tid] = src[tid];
            if (tid < 248) dst[tid + 256] = src[tid + 256];
        }
        __syncthreads();

#pragma unroll
        for (int ch = 0; ch < 8; ch++) {
            float xv[9];
#pragma unroll
            for (int t = 0; t < 9; t++)
                xv[t] = xs[ch][(ty + t / 3) * 18 + tx + (t % 3)];
#pragma unroll
            for (int t = 0; t < 9; t++) {
                ull xd = pk2(xv[t], xv[t]);
#pragma unroll
                for (int q = 0; q < 7; q++) {
                    float4 w4 = *(const float4*)&ws[ch * 252 + t * 28 + q * 4];
                    ull wlo = pk2(w4.x, w4.y);
                    ull whi = pk2(w4.z, w4.w);
                    fma2(acc2[2 * q], xd, wlo);
                    fma2(acc2[2 * q + 1], xd, whi);
                }
            }
        }
    }

    float acc[28];
#pragma unroll
    for (int j = 0; j < 14; j++) upk2(acc2[j], acc[2 * j], acc[2 * j + 1]);

    int h = h0 + ty, w = w0 + tx;
    float* op = g_offs + ((size_t)b * HWn + h * Wn + w) * 27;
#pragma unroll
    for (int kk = 0; kk < 9; kk++) {
        float dy = acc[2 * kk]     + b_om[2 * kk];
        float dx = acc[2 * kk + 1] + b_om[2 * kk + 1];
        float mv = acc[18 + kk]    + b_om[18 + kk];
        mv = 1.f / (1.f + expf(-mv));
        op[3 * kk]     = dy;
        op[3 * kk + 1] = dx;
        op[3 * kk + 2] = mv;
    }
}

// ---------------------------------------------------------------------------
// K2: fused bilinear sampling + (pix x o) GEMM + BN + SiLU
// block: 128 pixel tile (8 rows x 16 cols) x 64 o, 256 threads
// micro-tile 8pix x 4o per thread, packed f32x2; 2 barriers per kk
// Dynamic shared memory (54.3 KB > 48 KB static cap)
// ---------------------------------------------------------------------------
__global__ void __launch_bounds__(256) main_k(const float* __restrict__ gamma,
                                              const float* __restrict__ beta,
                                              const float* __restrict__ rmean,
                                              const float* __restrict__ rvar,
                                              float* __restrict__ out) {
    extern __shared__ __align__(16) char smem[];
    int*   s_off = (int*)smem;                    // [4][128]
    float* s_bw  = (float*)(smem + 2048);         // [4][128]
    float* sA    = (float*)(smem + 4096);         // [64][132]
    float* sW    = (float*)(smem + 37888);        // [64][64]

    int b  = blockIdx.z;
    int h0 = blockIdx.y * 8;
    int w0 = blockIdx.x * 16;
    int tid = threadIdx.x;
    int o_grp = tid & 15;      // o micro-tile -> o0 = o_grp*4
    int p_grp = tid >> 4;      // pix micro-tile -> pix0 = p_grp*8
    int pix = tid >> 1, cv = tid & 1;   // staging roles (2 threads / pixel)

    ull acc2[16];
#pragma unroll
    for (int i = 0; i < 16; i++) acc2[i] = 0ull;

    const float* xb = g_xt + (size_t)b * HWn * Cn;

    for (int kk = 0; kk < 9; kk++) {
        // --- per-kk coords: 128 threads, one per pixel ---
        if (tid < 128) {
            int prow = tid >> 4, pcol = tid & 15;
            int ho = h0 + prow, wo = w0 + pcol;
            const float* op = g_offs + ((size_t)b * HWn + ho * Wn + wo) * 27 + 3 * kk;
            float dy = op[0], dx = op[1], m = op[2];
            float py = (float)(ho - 1 + kk / 3) + dy;
            float px = (float)(wo - 1 + kk % 3) + dx;
            float y0f = floorf(py), x0f = floorf(px);
            float ly = py - y0f, lx = px - x0f;
            int y0 = (int)y0f, x0 = (int)x0f;
            int y1 = y0 + 1, x1 = x0 + 1;
            float vy0 = (y0 >= 0 && y0 < Hn) ? 1.f : 0.f;
            float vy1 = (y1 >= 0 && y1 < Hn) ? 1.f : 0.f;
            float vx0 = (x0 >= 0 && x0 < Wn) ? 1.f : 0.f;
            float vx1 = (x1 >= 0 && x1 < Wn) ? 1.f : 0.f;
            s_bw[0 * 128 + tid] = (1.f - ly) * (1.f - lx) * m * vy0 * vx0;
            s_bw[1 * 128 + tid] = (1.f - ly) * lx         * m * vy0 * vx1;
            s_bw[2 * 128 + tid] = ly * (1.f - lx)         * m * vy1 * vx0;
            s_bw[3 * 128 + tid] = ly * lx                 * m * vy1 * vx1;
            int y0c = min(max(y0, 0), Hn - 1), y1c = min(max(y1, 0), Hn - 1);
            int x0c = min(max(x0, 0), Wn - 1), x1c = min(max(x1, 0), Wn - 1);
            s_off[0 * 128 + tid] = (y0c * Wn + x0c) * Cn;
            s_off[1 * 128 + tid] = (y0c * Wn + x1c) * Cn;
            s_off[2 * 128 + tid] = (y1c * Wn + x0c) * Cn;
            s_off[3 * 128 + tid] = (y1c * Wn + x1c) * Cn;
        }
        __syncthreads();

        // --- stage sampled tile sA (each thread: 32 channels of 1 pixel) ---
        {
            int q00 = s_off[0 * 128 + pix], q01 = s_off[1 * 128 + pix];
            int q10 = s_off[2 * 128 + pix], q11 = s_off[3 * 128 + pix];
            float b00 = s_bw[0 * 128 + pix], b01 = s_bw[1 * 128 + pix];
            float b10 = s_bw[2 * 128 + pix], b11 = s_bw[3 * 128 + pix];
            ull pw00 = pk2(b00, b00), pw01 = pk2(b01, b01);
            ull pw10 = pk2(b10, b10), pw11 = pk2(b11, b11);
#pragma unroll
            for (int g = 0; g < 8; g++) {
                int c = g * 8 + cv * 4;
                float4 v00 = *(const float4*)(xb + q00 + c);
                float4 v01 = *(const float4*)(xb + q01 + c);
                float4 v10 = *(const float4*)(xb + q10 + c);
                float4 v11 = *(const float4*)(xb + q11 + c);
                ull r0 = mul2(pw00, pk2(v00.x, v00.y));
                fma2(r0, pw01, pk2(v01.x, v01.y));
                fma2(r0, pw10, pk2(v10.x, v10.y));
                fma2(r0, pw11, pk2(v11.x, v11.y));
                ull r1 = mul2(pw00, pk2(v00.z, v00.w));
                fma2(r1, pw01, pk2(v01.z, v01.w));
                fma2(r1, pw10, pk2(v10.z, v10.w));
                fma2(r1, pw11, pk2(v11.z, v11.w));
                float f0, f1, f2, f3;
                upk2(r0, f0, f1); upk2(r1, f2, f3);
                sA[(c + 0) * 132 + pix] = f0;
                sA[(c + 1) * 132 + pix] = f1;
                sA[(c + 2) * 132 + pix] = f2;
                sA[(c + 3) * 132 + pix] = f3;
            }
            // W tile: 4096 floats, coalesced float4
            const float4* src = (const float4*)(g_wt + kk * Cn * Cn);
            float4* dst = (float4*)sW;
#pragma unroll
            for (int i = 0; i < 4; i++) dst[tid + i * 256] = src[tid + i * 256];
        }
        __syncthreads();

        // --- GEMM: 64 K-steps, 8p x 4o micro-tile, packed f32x2 ---
#pragma unroll 8
        for (int cl = 0; cl < 64; cl++) {
            const float* arow = &sA[cl * 132 + p_grp * 8];
            float4 a0 = *(const float4*)(arow);
            float4 a1 = *(const float4*)(arow + 4);
            float4 wv = *(const float4*)&sW[cl * 64 + o_grp * 4];
            ull wlo = pk2(wv.x, wv.y), whi = pk2(wv.z, wv.w);
            ull sp0 = pk2(a0.x, a0.x), sp1 = pk2(a0.y, a0.y);
            ull sp2 = pk2(a0.z, a0.z), sp3 = pk2(a0.w, a0.w);
            ull sp4 = pk2(a1.x, a1.x), sp5 = pk2(a1.y, a1.y);
            ull sp6 = pk2(a1.z, a1.z), sp7 = pk2(a1.w, a1.w);
            fma2(acc2[0],  sp0, wlo); fma2(acc2[1],  sp0, whi);
            fma2(acc2[2],  sp1, wlo); fma2(acc2[3],  sp1, whi);
            fma2(acc2[4],  sp2, wlo); fma2(acc2[5],  sp2, whi);
            fma2(acc2[6],  sp3, wlo); fma2(acc2[7],  sp3, whi);
            fma2(acc2[8],  sp4, wlo); fma2(acc2[9],  sp4, whi);
            fma2(acc2[10], sp5, wlo); fma2(acc2[11], sp5, whi);
            fma2(acc2[12], sp6, wlo); fma2(acc2[13], sp6, whi);
            fma2(acc2[14], sp7, wlo); fma2(acc2[15], sp7, whi);
        }
    }

    // --- epilogue: BN + SiLU, write NCHW ---
    float a[8][4];
#pragma unroll
    for (int p = 0; p < 8; p++) {
        upk2(acc2[p * 2 + 0], a[p][0], a[p][1]);
        upk2(acc2[p * 2 + 1], a[p][2], a[p][3]);
    }

    int o0 = o_grp * 4;
    // pixels pix0..pix0+7: row = h0 + (p_grp>>1), cols = w0 + (p_grp&1)*8 + p
    int ho = h0 + (p_grp >> 1);
    int wc = w0 + (p_grp & 1) * 8;
#pragma unroll
    for (int j = 0; j < 4; j++) {
        int o = o0 + j;
        float sc = gamma[o] * rsqrtf(rvar[o] + 1e-5f);
        float sh = beta[o] - rmean[o] * sc;
        float* orow = &out[(((size_t)b * Cn + o) * Hn + ho) * Wn + wc];
        float4 r0, r1;
        float v;
        v = a[0][j] * sc + sh; r0.x = v / (1.f + expf(-v));
        v = a[1][j] * sc + sh; r0.y = v / (1.f + expf(-v));
        v = a[2][j] * sc + sh; r0.z = v / (1.f + expf(-v));
        v = a[3][j] * sc + sh; r0.w = v / (1.f + expf(-v));
        v = a[4][j] * sc + sh; r1.x = v / (1.f + expf(-v));
        v = a[5][j] * sc + sh; r1.y = v / (1.f + expf(-v));
        v = a[6][j] * sc + sh; r1.z = v / (1.f + expf(-v));
        v = a[7][j] * sc + sh; r1.w = v / (1.f + expf(-v));
        *(float4*)(orow)     = r0;
        *(float4*)(orow + 4) = r1;
    }
}

// ---------------------------------------------------------------------------
extern "C" void kernel_launch(void* const* d_in, const int* in_sizes, int n_in,
                              void* d_out, int out_size) {
    const float* x      = (const float*)d_in[0];
    const float* w_om   = (const float*)d_in[1];
    const float* b_om   = (const float*)d_in[2];
    const float* w_conv = (const float*)d_in[3];
    const float* gamma  = (const float*)d_in[4];
    const float* beta   = (const float*)d_in[5];
    const float* rmean  = (const float*)d_in[6];
    const float* rvar   = (const float*)d_in[7];
    float* out = (float*)d_out;

    cudaFuncSetAttribute(main_k, cudaFuncAttributeMaxDynamicSharedMemorySize,
                         MAINK_SMEM);

    transpose_k<<<dim3(HWn / 32, Cn / 32, Bn), dim3(32, 8)>>>(x);
    prep_w_k<<<(KKn * Cn * Cn + 1023) / 1024, 1024>>>(w_conv, w_om);
    om_conv_k<<<dim3(Wn / 16, Hn / 16, Bn), 256>>>(x, b_om);
    main_k<<<dim3(Wn / 16, Hn / 8, Bn), 256, MAINK_SMEM>>>(gamma, beta, rmean,
                                                           rvar, out);
}